// round 10
// baseline (speedup 1.0000x reference)
#include <cuda_runtime.h>

#define DIM  160
#define RP   164   // padded smem row (floats); 656B
#define NB   2

// scale0: k=10 s=2 O=71 | scale1: k=20 s=5 O=25 | scale2: k=40 s=10 O=9
#define O0 71
#define O1 25
#define O2 9
#define NZ0 80
#define NZ1c 160
#define NZ2 80

#define FS0 (NB*NZ0*O0*O0)
#define FS1 (NB*NZ1c*O1*O1)
#define FS2 (NB*NZ2*O2*O2)
#define OFF0 0
#define OFF1 (5*FS0)
#define OFF2 (OFF1 + 5*FS1)

#define N3_0 (NB*O0*O0*O0)
#define N3_1 (NB*O1*O1*O1)
#define N3_2 (NB*O2*O2*O2)

#define NSTRIP0 24
#define STRIP0  3
#define NT0S   (NB*NSTRIP0*O0*O0)          // 241,968
#define NBLK0S ((NT0S + 255) / 256)        // 946
#define NBLK1  ((N3_1 + 255) / 256)        // 123
#define NBLK2  ((N3_2 + 255) / 256)        //   6
#define TOTBLK (NBLK0S + NBLK1 + NBLK2)

#define PB0 0
#define PB1 960
#define PB2 1088

__device__ float g_bufB[OFF2 + 5*FS2];   // ~20.4 MB
__device__ float g_partials[1280];
__device__ unsigned int g_count = 0;

#define RAWF (2*16*RP)    // 16 rows x 2 vols = 5248 floats

// ---------------------------------------------------------------------------
// row load/store helpers (warp-cooperative, float4)
// ---------------------------------------------------------------------------
__device__ __forceinline__ void ldrow(const float* __restrict__ p, int lane,
                                      float4& r0, float4& r1) {
    const float4* q = (const float4*)p;
    r0 = q[lane];
    if (lane < 8) r1 = q[32 + lane];
}
__device__ __forceinline__ void strow(float* d, int lane,
                                      const float4& r0, const float4& r1) {
    float4* q = (float4*)d;
    q[lane] = r0;
    if (lane < 8) q[32 + lane] = r1;
}

// window sum of 5 field products over K taps (taps step 2 in z2)
template<int K>
__device__ __forceinline__ void win5(const float* xr, const float* yr, int z2s,
                                     float* out, int stride) {
    float a0 = 0.f, a1 = 0.f, a2 = 0.f, a3 = 0.f, a4 = 0.f;
#pragma unroll
    for (int t = 0; t < K; t++) {
        float xv = xr[z2s + 2 * t];
        float yv = yr[z2s + 2 * t];
        a0 += xv; a1 += yv; a2 += xv * xv; a3 += yv * yv; a4 += xv * yv;
    }
    out[0 * stride] = a0;
    out[1 * stride] = a1;
    out[2 * stride] = a2;
    out[3 * stride] = a3;
    out[4 * stride] = a4;
}

// ---------------------------------------------------------------------------
// fused_sc1: one block per (b,z0), 512 threads, 10 batches of 16 rows.
// Phase-2 via parity-prefix checkpoints: C[m] = prefix of parity-(m%2) plane
// sums over planes < 5m; window W(o1) = C[o1+8] - C[o1].
// smem: raw 5248 + wrow 16*125 + C 33*125 = 11,373 floats = 45.5 KB.
// ---------------------------------------------------------------------------
__global__ __launch_bounds__(512) void fused_sc1(const float* __restrict__ x,
                                                 const float* __restrict__ y) {
    extern __shared__ float sm[];
    float* raw  = sm;                 // x rows [16][RP], y rows [16][RP]
    float* wrow = sm + RAWF;          // [16][5*25]
    float* Cchk = wrow + 16 * 125;    // [33][5*25]

    int z0 = blockIdx.x % DIM;
    int b  = blockIdx.x / DIM;
    int w    = threadIdx.x >> 5;
    int lane = threadIdx.x & 31;
    const float* xbase = x + (size_t)(b * DIM + z0) * DIM * DIM;
    const float* ybase = y + (size_t)(b * DIM + z0) * DIM * DIM;

    float Re = 0.f, Ro = 0.f;         // per-channel running parity sums

    float4 fx0, fx1, fy0, fy1;
    ldrow(xbase + (size_t)w * DIM, lane, fx0, fx1);
    ldrow(ybase + (size_t)w * DIM, lane, fy0, fy1);

    for (int ib = 0; ib < 10; ib++) {
        __syncthreads();                       // prev batch fully consumed
        strow(raw + w * RP,        lane, fx0, fx1);
        strow(raw + (16 + w) * RP, lane, fy0, fy1);
        if (ib < 9) {
            int z1 = (ib + 1) * 16 + w;
            ldrow(xbase + (size_t)z1 * DIM, lane, fx0, fx1);
            ldrow(ybase + (size_t)z1 * DIM, lane, fy0, fy1);
        }
        __syncthreads();                       // rows visible
        if (threadIdx.x < 16 * O1) {
            int rl = threadIdx.x / O1;
            int o2 = threadIdx.x % O1;
            win5<20>(raw + rl * RP, raw + (16 + rl) * RP, 5 * o2,
                     wrow + rl * 125 + o2, O1);
        }
        __syncthreads();                       // wrow ready
        if (threadIdx.x < 125) {
            int ch = threadIdx.x;
#pragma unroll
            for (int rl = 0; rl < 16; rl++) {
                int z1 = ib * 16 + rl;
                if (z1 % 5 == 0) {
                    int m = z1 / 5;
                    Cchk[m * 125 + ch] = (m & 1) ? Ro : Re;
                }
                float v = wrow[rl * 125 + ch];
                if (z1 & 1) Ro += v; else Re += v;
            }
        }
    }
    if (threadIdx.x < 125)
        Cchk[32 * 125 + threadIdx.x] = Re;     // m=32 (even parity)
    __syncthreads();

    for (int item = threadIdx.x; item < 5 * O1 * O1; item += 512) {
        int f   = item / (O1 * O1);
        int rem = item % (O1 * O1);
        int o1  = rem / O1;
        int o2  = rem % O1;
        int ch  = f * O1 + o2;
        float v = Cchk[(o1 + 8) * 125 + ch] - Cchk[o1 * 125 + ch];
        g_bufB[OFF1 + f * FS1 + (((b * NZ1c) + z0) * O1 + o1) * O1 + o2] = v;
    }
}

// ---------------------------------------------------------------------------
// fused_sc02 (R9 body, standalone): even planes, CH0=36, 2 chunks,
// 512 threads, 5 batches of 16 even rows.
// ---------------------------------------------------------------------------
#define CH0 36
__global__ __launch_bounds__(512) void fused_sc02(const float* __restrict__ x,
                                                  const float* __restrict__ y) {
    extern __shared__ float sm[];
    const int NZ = 80;
    float* zwin0 = sm;                          // [80][5][CH0]
    float* zwin2 = sm + NZ * 5 * CH0;           // [80][5][9]
    float* raw   = zwin2 + NZ * 5 * O2;

    int bid = blockIdx.x;
    int ch  = bid & 1;  bid >>= 1;
    int z0i = bid % NZ;
    int b   = bid / NZ;
    int z0  = 2 * z0i;
    int obase = ch * CH0;
    int w    = threadIdx.x >> 5;
    int lane = threadIdx.x & 31;
    const float* xbase = x + (size_t)(b * DIM + z0) * DIM * DIM;
    const float* ybase = y + (size_t)(b * DIM + z0) * DIM * DIM;

    float4 fx0, fx1, fy0, fy1;
    ldrow(xbase + (size_t)(2 * w) * DIM, lane, fx0, fx1);
    ldrow(ybase + (size_t)(2 * w) * DIM, lane, fy0, fy1);

    for (int ib = 0; ib < 5; ib++) {
        int rb = ib * 16;
        __syncthreads();
        strow(raw + w * RP,        lane, fx0, fx1);
        strow(raw + (16 + w) * RP, lane, fy0, fy1);
        if (ib < 4) {
            int z1 = 2 * (rb + 16 + w);
            ldrow(xbase + (size_t)z1 * DIM, lane, fx0, fx1);
            ldrow(ybase + (size_t)z1 * DIM, lane, fy0, fy1);
        }
        __syncthreads();

        int nit = (ch == 0) ? (16 * CH0 + 16 * O2) : (16 * CH0);
        for (int it = threadIdx.x; it < nit; it += 512) {
            if (it < 16 * CH0) {
                int rl  = it / CH0;
                int o2l = it % CH0;
                int o2  = obase + o2l;
                if (o2 < O0)
                    win5<10>(raw + rl * RP, raw + (16 + rl) * RP, 2 * o2,
                             zwin0 + (size_t)(rb + rl) * 5 * CH0 + o2l, CH0);
            } else {
                int it2 = it - 16 * CH0;
                int rl = it2 / O2;
                int o2 = it2 % O2;
                win5<40>(raw + rl * RP, raw + (16 + rl) * RP, 10 * o2,
                         zwin2 + (size_t)(rb + rl) * 5 * O2 + o2, O2);
            }
        }
    }
    __syncthreads();

    {
        const int ITEMS = 5 * O0 * CH0;
        for (int item = threadIdx.x; item < ITEMS; item += 512) {
            int f   = item / (O0 * CH0);
            int rem = item % (O0 * CH0);
            int o1  = rem / CH0;
            int o2l = rem % CH0;
            int o2  = obase + o2l;
            if (o2 >= O0) continue;
            float acc = 0.f;
#pragma unroll
            for (int t = 0; t < 10; t++)
                acc += zwin0[(size_t)(o1 + t) * 5 * CH0 + f * CH0 + o2l];
            g_bufB[OFF0 + f * FS0 + (((b * NZ) + z0i) * O0 + o1) * O0 + o2] = acc;
        }
    }
    if (ch == 0) {
        const int ITEMS = 5 * O2 * O2;
        for (int item = threadIdx.x; item < ITEMS; item += 512) {
            int f   = item / (O2 * O2);
            int rem = item % (O2 * O2);
            int o1  = rem / O2;
            int o2  = rem % O2;
            float acc = 0.f;
#pragma unroll
            for (int t = 0; t < 40; t++)
                acc += zwin2[(size_t)(5 * o1 + t) * 5 * O2 + f * O2 + o2];
            g_bufB[OFF2 + f * FS2 + (((b * NZ) + z0i) * O2 + o1) * O2 + o2] = acc;
        }
    }
}

// ---------------------------------------------------------------------------
// pass34 + fused finalize
// ---------------------------------------------------------------------------
__device__ __forceinline__ float lncc_eval(float s0, float s1, float s2,
                                           float s3, float s4, float numel) {
    float xm = s0 / numel;
    float ym = s1 / numel;
    float cross = s4 - ym * s0 - xm * s1 + ym * xm * numel;
    float xvar  = s2 - 2.f * xm * s0 + xm * xm * numel;
    float yvar  = s3 - 2.f * ym * s1 + ym * ym * numel;
    return cross * cross / (xvar * yvar + 1e-5f);
}

template<int K, int O, int NZ, int B0, int TS, int OFF, int FS, int N3>
__device__ __forceinline__ float pass34_gather(int blk) {
    const float numel = (float)K * (float)K * (float)K;
    int idx = blk * 256 + threadIdx.x;
    if (idx >= N3) return 0.f;
    int o2 = idx % O;
    int r  = idx / O;
    int o1 = r % O;  r /= O;
    int o0 = r % O;
    int b  = r / O;
    int inbase = ((b * NZ + B0 * o0) * O + o1) * O + o2;
    const int tapstride = TS * O * O;
    float acc[5];
#pragma unroll
    for (int f = 0; f < 5; f++) {
        const float* p = g_bufB + OFF + f * FS + inbase;
        float a = 0.f;
#pragma unroll
        for (int t = 0; t < K; t++) a += p[t * tapstride];
        acc[f] = a;
    }
    return lncc_eval(acc[0], acc[1], acc[2], acc[3], acc[4], numel);
}

// sc0 strips: static fast path (3 windows), static tail (2 windows at o0s=69)
template<int NW>
__device__ __forceinline__ float strip0_fixed(const float* __restrict__ p0,
                                              int o0s) {
    const int PS = O0 * O0;
    float a[5];
    // prologue: 9 planes
#pragma unroll
    for (int f = 0; f < 5; f++) a[f] = 0.f;
#pragma unroll
    for (int j = 0; j < 9; j++) {
        int off = (o0s + j) * PS;
#pragma unroll
        for (int f = 0; f < 5; f++) a[f] += p0[off + f * FS0];
    }
    float vsum = 0.f;
#pragma unroll
    for (int s = 0; s < NW; s++) {
        int offl = (o0s + 9 + s) * PS;      // leading plane
#pragma unroll
        for (int f = 0; f < 5; f++) a[f] += p0[offl + f * FS0];
        vsum += lncc_eval(a[0], a[1], a[2], a[3], a[4], 1000.0f);
        int offt = (o0s + s) * PS;          // trailing plane
#pragma unroll
        for (int f = 0; f < 5; f++) a[f] -= p0[offt + f * FS0];
    }
    return vsum;
}

__device__ __forceinline__ float pass34_strip0(int blk) {
    int idx = blk * 256 + threadIdx.x;
    if (idx >= NT0S) return 0.f;
    int o2 = idx % O0;
    int r  = idx / O0;
    int o1 = r % O0;  r /= O0;
    int strip = r % NSTRIP0;
    int b     = r / NSTRIP0;
    int o0s = strip * STRIP0;
    const float* p0 = g_bufB + OFF0 + ((b * NZ0) * O0 + o1) * O0 + o2;
    if (o0s + STRIP0 <= O0) return strip0_fixed<3>(p0, o0s);  // strips 0..22
    return strip0_fixed<2>(p0, o0s);                          // strip 23 (69,70)
}

__global__ __launch_bounds__(256) void pass34_all(float* __restrict__ out) {
    int bb = blockIdx.x;
    float v;
    int pslot;
    if (bb < NBLK0S) {
        v = pass34_strip0(bb);
        pslot = PB0 + bb;
    } else if (bb < NBLK0S + NBLK1) {
        v = pass34_gather<20, O1, NZ1c, 5, 2, OFF1, FS1, N3_1>(bb - NBLK0S);
        pslot = PB1 + (bb - NBLK0S);
    } else {
        v = pass34_gather<40, O2, NZ2, 5, 1, OFF2, FS2, N3_2>(bb - NBLK0S - NBLK1);
        pslot = PB2 + (bb - NBLK0S - NBLK1);
    }

    __shared__ float wsum[8];
    int lane = threadIdx.x & 31;
    int wid  = threadIdx.x >> 5;
#pragma unroll
    for (int o = 16; o > 0; o >>= 1) v += __shfl_down_sync(0xffffffffu, v, o);
    if (lane == 0) wsum[wid] = v;
    __syncthreads();
    if (wid == 0) {
        v = (lane < 8) ? wsum[lane] : 0.f;
#pragma unroll
        for (int o = 4; o > 0; o >>= 1) v += __shfl_down_sync(0xffffffffu, v, o);
        if (lane == 0) g_partials[pslot] = v;
    }

    __shared__ bool isLast;
    __threadfence();
    if (threadIdx.x == 0) {
        unsigned int old = atomicAdd(&g_count, 1u);
        isLast = (old == TOTBLK - 1);
    }
    __syncthreads();
    if (!isLast) return;
    __threadfence();

    __shared__ float sh[256];
    const int   pbase[3] = {PB0, PB1, PB2};
    const int   nblk[3]  = {NBLK0S, NBLK1, NBLK2};
    const float ninv[3]  = {1.0f / N3_0, 1.0f / N3_1, 1.0f / N3_2};
    const float wsc[3]   = {0.1f, 0.3f, 0.6f};
    float total = 0.f;
    for (int sc = 0; sc < 3; sc++) {
        float a = 0.f;
        for (int i = threadIdx.x; i < nblk[sc]; i += 256) a += g_partials[pbase[sc] + i];
        sh[threadIdx.x] = a;
        __syncthreads();
#pragma unroll
        for (int st = 128; st > 0; st >>= 1) {
            if (threadIdx.x < st) sh[threadIdx.x] += sh[threadIdx.x + st];
            __syncthreads();
        }
        if (threadIdx.x == 0) total += (1.0f - sh[0] * ninv[sc]) * wsc[sc];
        __syncthreads();
    }
    if (threadIdx.x == 0) {
        out[0] = total;
        g_count = 0;
    }
}

#define SMEM_SC1  ((RAWF + 16*125 + 33*125) * (int)sizeof(float))             // 45,492 B
#define SMEM_SC02 ((NZ0*5*CH0 + NZ0*5*O2 + RAWF) * (int)sizeof(float))        // 92,992 B

extern "C" void kernel_launch(void* const* d_in, const int* in_sizes, int n_in,
                              void* d_out, int out_size) {
    const float* x = (const float*)d_in[0];
    const float* y = (const float*)d_in[1];
    float* out = (float*)d_out;

    cudaFuncSetAttribute(fused_sc1,
                         cudaFuncAttributeMaxDynamicSharedMemorySize, SMEM_SC1);
    cudaFuncSetAttribute(fused_sc02,
                         cudaFuncAttributeMaxDynamicSharedMemorySize, SMEM_SC02);

    fused_sc1 <<<NB * DIM,     512, SMEM_SC1 >>>(x, y);
    fused_sc02<<<NB * NZ0 * 2, 512, SMEM_SC02>>>(x, y);
    pass34_all<<<TOTBLK, 256>>>(out);
}

// round 12
// speedup vs baseline: 1.0589x; 1.0589x over previous
#include <cuda_runtime.h>

#define DIM  160
#define RP   164   // padded smem row (floats)
#define NB   2

// scale0: k=10 s=2 O=71 | scale1: k=20 s=5 O=25 | scale2: k=40 s=10 O=9
#define O0 71
#define O1 25
#define O2 9
#define NZ0 80
#define NZ1c 160
#define NZ2 80

#define FS0 (NB*NZ0*O0*O0)
#define FS1 (NB*NZ1c*O1*O1)
#define FS2 (NB*NZ2*O2*O2)
#define OFF0 0
#define OFF1 (5*FS0)
#define OFF2 (OFF1 + 5*FS1)

#define N3_0 (NB*O0*O0*O0)
#define N3_1 (NB*O1*O1*O1)
#define N3_2 (NB*O2*O2*O2)

#define NSTRIP0 24
#define STRIP0  3
#define NT0S   (NB*NSTRIP0*O0*O0)          // 241,968
#define NBLK0S ((NT0S + 255) / 256)        // 946
#define NBLK1  ((N3_1 + 255) / 256)        // 123
#define NBLK2  ((N3_2 + 255) / 256)        //   6
#define TOTBLK (NBLK0S + NBLK1 + NBLK2)

#define PB0 0
#define PB1 960
#define PB2 1088

__device__ float g_bufB[OFF2 + 5*FS2];   // ~20.4 MB
__device__ float g_partials[1280];
__device__ unsigned int g_count = 0;

#define RAWF (2*16*RP)    // 16 rows x 2 vols = 5248 floats

// fused grid: sc1 halves first, then sc02 (3 chunks)
#define G1  (NB*DIM*2)     // 640
#define G02 (NB*NZ0*3)     // 480
#define GALL (G1 + G02)
#define CH0 24

// sc1 zwin region padded to 16B boundary: 99*125 = 12375 -> 12376 floats
#define ZWPAD1 12376

// uniform smem: sc02 = 80*5*24 + 80*5*9 + 5248 = 18448 floats
//               sc1  = 12376 + 5248          = 17624 floats
#define SMEM_ALL ((NZ0*5*CH0 + NZ0*5*O2 + RAWF) * (int)sizeof(float))

// ---------------------------------------------------------------------------
__device__ __forceinline__ void ldrow(const float* __restrict__ p, int lane,
                                      float4& r0, float4& r1) {
    const float4* q = (const float4*)p;
    r0 = q[lane];
    if (lane < 8) r1 = q[32 + lane];
}
__device__ __forceinline__ void strow(float* d, int lane,
                                      const float4& r0, const float4& r1) {
    float4* q = (float4*)d;
    q[lane] = r0;
    if (lane < 8) q[32 + lane] = r1;
}

template<int K>
__device__ __forceinline__ void win5(const float* xr, const float* yr, int z2s,
                                     float* out, int stride) {
    float a0 = 0.f, a1 = 0.f, a2 = 0.f, a3 = 0.f, a4 = 0.f;
#pragma unroll
    for (int t = 0; t < K; t++) {
        float xv = xr[z2s + 2 * t];
        float yv = yr[z2s + 2 * t];
        a0 += xv; a1 += yv; a2 += xv * xv; a3 += yv * yv; a4 += xv * yv;
    }
    out[0 * stride] = a0;
    out[1 * stride] = a1;
    out[2 * stride] = a2;
    out[3 * stride] = a3;
    out[4 * stride] = a4;
}

// ---------------------------------------------------------------------------
// sc1 half-body: windows o1 in [O1LO, O1LO+NW), planes z1 in [ZS, ZS+NR).
// zwin[rel][5][25], rel = z1 - ZS; window wi taps = rel planes 5*wi + 2t.
// ---------------------------------------------------------------------------
__device__ __forceinline__ void body_sc1(int bid, const float* __restrict__ x,
                                         const float* __restrict__ y, float* sm) {
    int half = bid & 1;  bid >>= 1;
    int z0 = bid % DIM;
    int b  = bid / DIM;
    const int ZS   = half ? 65 : 0;
    const int NR   = half ? 94 : 99;
    const int O1LO = half ? 13 : 0;
    const int NW   = half ? 12 : 13;
    const int NBATCH = (NR + 15) / 16;

    float* zwin = sm;                    // [NR][5][25] (<= 99*125)
    float* raw  = sm + ZWPAD1;           // 16B-aligned

    int w    = threadIdx.x >> 5;
    int lane = threadIdx.x & 31;
    const float* xbase = x + (size_t)(b * DIM + z0) * DIM * DIM;
    const float* ybase = y + (size_t)(b * DIM + z0) * DIM * DIM;

    float4 fx0, fx1, fy0, fy1;
    ldrow(xbase + (size_t)(ZS + w) * DIM, lane, fx0, fx1);
    ldrow(ybase + (size_t)(ZS + w) * DIM, lane, fy0, fy1);

    for (int ib = 0; ib < NBATCH; ib++) {
        int rb = ib * 16;
        __syncthreads();
        strow(raw + w * RP,        lane, fx0, fx1);
        strow(raw + (16 + w) * RP, lane, fy0, fy1);
        int nrel = rb + 16 + w;
        if (ib < NBATCH - 1 && nrel < NR) {
            ldrow(xbase + (size_t)(ZS + nrel) * DIM, lane, fx0, fx1);
            ldrow(ybase + (size_t)(ZS + nrel) * DIM, lane, fy0, fy1);
        }
        __syncthreads();
        if (threadIdx.x < 16 * O1) {
            int rl = threadIdx.x / O1;
            int o2 = threadIdx.x % O1;
            if (rb + rl < NR)
                win5<20>(raw + rl * RP, raw + (16 + rl) * RP, 5 * o2,
                         zwin + (size_t)(rb + rl) * 125 + o2, O1);
        }
    }
    __syncthreads();

    const int ITEMS = 5 * NW * O1;
    for (int item = threadIdx.x; item < ITEMS; item += 512) {
        int f   = item / (NW * O1);
        int rem = item % (NW * O1);
        int wi  = rem / O1;
        int o2  = rem % O1;
        float acc = 0.f;
#pragma unroll
        for (int t = 0; t < 20; t++)
            acc += zwin[(size_t)(5 * wi + 2 * t) * 125 + f * O1 + o2];
        int o1g = O1LO + wi;
        g_bufB[OFF1 + f * FS1 + (((b * NZ1c) + z0) * O1 + o1g) * O1 + o2] = acc;
    }
}

// ---------------------------------------------------------------------------
// sc02 body: even planes (z = 2*zi), CH0=24, 3 chunks; zwin2 in chunk 0.
// ---------------------------------------------------------------------------
__device__ __forceinline__ void body_sc02(int bid, const float* __restrict__ x,
                                          const float* __restrict__ y, float* sm) {
    const int NZ = 80;
    float* zwin0 = sm;                          // [80][5][CH0] = 9600
    float* zwin2 = sm + NZ * 5 * CH0;           // [80][5][9]   = 3600
    float* raw   = zwin2 + NZ * 5 * O2;         // offset 13200 floats (16B ok)

    int ch  = bid % 3;  bid /= 3;
    int z0i = bid % NZ;
    int b   = bid / NZ;
    int z0  = 2 * z0i;
    int obase = ch * CH0;                       // 0, 24, 48
    int w    = threadIdx.x >> 5;
    int lane = threadIdx.x & 31;
    const float* xbase = x + (size_t)(b * DIM + z0) * DIM * DIM;
    const float* ybase = y + (size_t)(b * DIM + z0) * DIM * DIM;

    float4 fx0, fx1, fy0, fy1;
    ldrow(xbase + (size_t)(2 * w) * DIM, lane, fx0, fx1);
    ldrow(ybase + (size_t)(2 * w) * DIM, lane, fy0, fy1);

    for (int ib = 0; ib < 5; ib++) {
        int rb = ib * 16;
        __syncthreads();
        strow(raw + w * RP,        lane, fx0, fx1);
        strow(raw + (16 + w) * RP, lane, fy0, fy1);
        if (ib < 4) {
            int z1 = 2 * (rb + 16 + w);
            ldrow(xbase + (size_t)z1 * DIM, lane, fx0, fx1);
            ldrow(ybase + (size_t)z1 * DIM, lane, fy0, fy1);
        }
        __syncthreads();

        int nit = (ch == 0) ? (16 * CH0 + 16 * O2) : (16 * CH0);
        for (int it = threadIdx.x; it < nit; it += 512) {
            if (it < 16 * CH0) {
                int rl  = it / CH0;
                int o2l = it % CH0;
                int o2  = obase + o2l;
                if (o2 < O0)
                    win5<10>(raw + rl * RP, raw + (16 + rl) * RP, 2 * o2,
                             zwin0 + (size_t)(rb + rl) * 5 * CH0 + o2l, CH0);
            } else {
                int it2 = it - 16 * CH0;
                int rl = it2 / O2;
                int o2 = it2 % O2;
                win5<40>(raw + rl * RP, raw + (16 + rl) * RP, 10 * o2,
                         zwin2 + (size_t)(rb + rl) * 5 * O2 + o2, O2);
            }
        }
    }
    __syncthreads();

    // phase2 sc0: taps = 10 consecutive compact planes o1..o1+9
    {
        const int ITEMS = 5 * O0 * CH0;
        for (int item = threadIdx.x; item < ITEMS; item += 512) {
            int f   = item / (O0 * CH0);
            int rem = item % (O0 * CH0);
            int o1  = rem / CH0;
            int o2l = rem % CH0;
            int o2  = obase + o2l;
            if (o2 >= O0) continue;
            float acc = 0.f;
#pragma unroll
            for (int t = 0; t < 10; t++)
                acc += zwin0[(size_t)(o1 + t) * 5 * CH0 + f * CH0 + o2l];
            g_bufB[OFF0 + f * FS0 + (((b * NZ) + z0i) * O0 + o1) * O0 + o2] = acc;
        }
    }
    // phase2 sc2: taps = compact planes 5*o1 + t, t<40 (chunk 0 only)
    if (ch == 0) {
        const int ITEMS = 5 * O2 * O2;
        for (int item = threadIdx.x; item < ITEMS; item += 512) {
            int f   = item / (O2 * O2);
            int rem = item % (O2 * O2);
            int o1  = rem / O2;
            int o2  = rem % O2;
            float acc = 0.f;
#pragma unroll
            for (int t = 0; t < 40; t++)
                acc += zwin2[(size_t)(5 * o1 + t) * 5 * O2 + f * O2 + o2];
            g_bufB[OFF2 + f * FS2 + (((b * NZ) + z0i) * O2 + o1) * O2 + o2] = acc;
        }
    }
}

__global__ __launch_bounds__(512, 3) void fused_all(const float* __restrict__ x,
                                                    const float* __restrict__ y) {
    extern __shared__ float sm[];
    int b = blockIdx.x;
    if (b < G1) body_sc1(b, x, y, sm);
    else        body_sc02(b - G1, x, y, sm);
}

// ---------------------------------------------------------------------------
// pass34 + fused finalize
// ---------------------------------------------------------------------------
__device__ __forceinline__ float lncc_eval(float s0, float s1, float s2,
                                           float s3, float s4, float numel) {
    float xm = s0 / numel;
    float ym = s1 / numel;
    float cross = s4 - ym * s0 - xm * s1 + ym * xm * numel;
    float xvar  = s2 - 2.f * xm * s0 + xm * xm * numel;
    float yvar  = s3 - 2.f * ym * s1 + ym * ym * numel;
    return cross * cross / (xvar * yvar + 1e-5f);
}

template<int K, int O, int NZ, int B0, int TS, int OFF, int FS, int N3>
__device__ __forceinline__ float pass34_gather(int blk) {
    const float numel = (float)K * (float)K * (float)K;
    int idx = blk * 256 + threadIdx.x;
    if (idx >= N3) return 0.f;
    int o2 = idx % O;
    int r  = idx / O;
    int o1 = r % O;  r /= O;
    int o0 = r % O;
    int b  = r / O;
    int inbase = ((b * NZ + B0 * o0) * O + o1) * O + o2;
    const int tapstride = TS * O * O;
    float acc[5];
#pragma unroll
    for (int f = 0; f < 5; f++) {
        const float* p = g_bufB + OFF + f * FS + inbase;
        float a = 0.f;
#pragma unroll
        for (int t = 0; t < K; t++) a += p[t * tapstride];
        acc[f] = a;
    }
    return lncc_eval(acc[0], acc[1], acc[2], acc[3], acc[4], numel);
}

template<int NW>
__device__ __forceinline__ float strip0_fixed(const float* __restrict__ p0,
                                              int o0s) {
    const int PS = O0 * O0;
    float a[5];
#pragma unroll
    for (int f = 0; f < 5; f++) a[f] = 0.f;
#pragma unroll
    for (int j = 0; j < 9; j++) {
        int off = (o0s + j) * PS;
#pragma unroll
        for (int f = 0; f < 5; f++) a[f] += p0[off + f * FS0];
    }
    float vsum = 0.f;
#pragma unroll
    for (int s = 0; s < NW; s++) {
        int offl = (o0s + 9 + s) * PS;
#pragma unroll
        for (int f = 0; f < 5; f++) a[f] += p0[offl + f * FS0];
        vsum += lncc_eval(a[0], a[1], a[2], a[3], a[4], 1000.0f);
        int offt = (o0s + s) * PS;
#pragma unroll
        for (int f = 0; f < 5; f++) a[f] -= p0[offt + f * FS0];
    }
    return vsum;
}

__device__ __forceinline__ float pass34_strip0(int blk) {
    int idx = blk * 256 + threadIdx.x;
    if (idx >= NT0S) return 0.f;
    int o2 = idx % O0;
    int r  = idx / O0;
    int o1 = r % O0;  r /= O0;
    int strip = r % NSTRIP0;
    int b     = r / NSTRIP0;
    int o0s = strip * STRIP0;
    const float* p0 = g_bufB + OFF0 + ((b * NZ0) * O0 + o1) * O0 + o2;
    if (o0s + STRIP0 <= O0) return strip0_fixed<3>(p0, o0s);
    return strip0_fixed<2>(p0, o0s);
}

__global__ __launch_bounds__(256) void pass34_all(float* __restrict__ out) {
    int bb = blockIdx.x;
    float v;
    int pslot;
    if (bb < NBLK0S) {
        v = pass34_strip0(bb);
        pslot = PB0 + bb;
    } else if (bb < NBLK0S + NBLK1) {
        v = pass34_gather<20, O1, NZ1c, 5, 2, OFF1, FS1, N3_1>(bb - NBLK0S);
        pslot = PB1 + (bb - NBLK0S);
    } else {
        v = pass34_gather<40, O2, NZ2, 5, 1, OFF2, FS2, N3_2>(bb - NBLK0S - NBLK1);
        pslot = PB2 + (bb - NBLK0S - NBLK1);
    }

    __shared__ float wsum[8];
    int lane = threadIdx.x & 31;
    int wid  = threadIdx.x >> 5;
#pragma unroll
    for (int o = 16; o > 0; o >>= 1) v += __shfl_down_sync(0xffffffffu, v, o);
    if (lane == 0) wsum[wid] = v;
    __syncthreads();
    if (wid == 0) {
        v = (lane < 8) ? wsum[lane] : 0.f;
#pragma unroll
        for (int o = 4; o > 0; o >>= 1) v += __shfl_down_sync(0xffffffffu, v, o);
        if (lane == 0) g_partials[pslot] = v;
    }

    __shared__ bool isLast;
    __threadfence();
    if (threadIdx.x == 0) {
        unsigned int old = atomicAdd(&g_count, 1u);
        isLast = (old == TOTBLK - 1);
    }
    __syncthreads();
    if (!isLast) return;
    __threadfence();

    __shared__ float sh[256];
    const int   pbase[3] = {PB0, PB1, PB2};
    const int   nblk[3]  = {NBLK0S, NBLK1, NBLK2};
    const float ninv[3]  = {1.0f / N3_0, 1.0f / N3_1, 1.0f / N3_2};
    const float wsc[3]   = {0.1f, 0.3f, 0.6f};
    float total = 0.f;
    for (int sc = 0; sc < 3; sc++) {
        float a = 0.f;
        for (int i = threadIdx.x; i < nblk[sc]; i += 256) a += g_partials[pbase[sc] + i];
        sh[threadIdx.x] = a;
        __syncthreads();
#pragma unroll
        for (int st = 128; st > 0; st >>= 1) {
            if (threadIdx.x < st) sh[threadIdx.x] += sh[threadIdx.x + st];
            __syncthreads();
        }
        if (threadIdx.x == 0) total += (1.0f - sh[0] * ninv[sc]) * wsc[sc];
        __syncthreads();
    }
    if (threadIdx.x == 0) {
        out[0] = total;
        g_count = 0;
    }
}

extern "C" void kernel_launch(void* const* d_in, const int* in_sizes, int n_in,
                              void* d_out, int out_size) {
    const float* x = (const float*)d_in[0];
    const float* y = (const float*)d_in[1];
    float* out = (float*)d_out;

    cudaFuncSetAttribute(fused_all,
                         cudaFuncAttributeMaxDynamicSharedMemorySize, SMEM_ALL);

    fused_all<<<GALL, 512, SMEM_ALL>>>(x, y);
    pass34_all<<<TOTBLK, 256>>>(out);
}